// round 11
// baseline (speedup 1.0000x reference)
#include <cuda_runtime.h>
#include <cuda_bf16.h>
#include <cstdint>
#include <math.h>

// Problem constants
#define Bb 128
#define Nn 512
#define Ff 128
#define Ll 64
#define Hh 128
#define Cc 10

// ---------------- scratch (device globals; no allocation allowed) ----------------
__device__ float g_inv_deg[Bb * Nn];            // 1/deg[b,k]
__device__ float g_YsT[Bb * Ll * Nn];           // transposed: [B][L=64][N=512], ((h@W_s)/deg)^T
__device__ float g_h1[Bb * Nn * Ll];            // elu(g @ Ys + b_s)  [B,N,L]
__device__ float2 g_q[Bb * Nn];                 // (h1@W_mu, h1@W_lv)/deg
__device__ float g_v[Bb * Nn];                  // sigmoid(beta*z)
__device__ float g_vd[Bb * Nn];                 // v / deg
__device__ float g_hp[Bb * Ll];                 // pooled features
__device__ float g_acc[4];                      // [kl_sum, mse_sum, nll_sum, acc_sum]

__device__ __forceinline__ float elu1(float x) { return x > 0.f ? x : expm1f(x); }

// ======================= PTX helpers (base ISA only) =============================
__device__ __forceinline__ uint32_t smem_u32(const void* p) {
    uint32_t a;
    asm("{ .reg .u64 t; cvta.to.shared.u64 t, %1; cvt.u32.u64 %0, t; }" : "=r"(a) : "l"(p));
    return a;
}
__device__ __forceinline__ void cp_async16(uint32_t dst, const void* src) {
    asm volatile("cp.async.cg.shared.global [%0], [%1], 16;" :: "r"(dst), "l"(src) : "memory");
}
#define CP_COMMIT()  asm volatile("cp.async.commit_group;" ::: "memory")
#define CP_WAIT_1()  asm volatile("cp.async.wait_group 1;" ::: "memory")
#define CP_WAIT_0()  asm volatile("cp.async.wait_group 0;" ::: "memory")

// load fp32 from smem and convert to tf32 (round-to-nearest)
__device__ __forceinline__ uint32_t lds_tf32(uint32_t addr) {
    float v;
    asm volatile("ld.shared.f32 %0, [%1];" : "=f"(v) : "r"(addr));
    uint32_t r;
    asm volatile("cvt.rna.tf32.f32 %0, %1;" : "=r"(r) : "f"(v));
    return r;
}
__device__ __forceinline__ void mma_tf32(float* c, const uint32_t* a, const uint32_t* b) {
    asm volatile(
        "mma.sync.aligned.m16n8k8.row.col.f32.tf32.tf32.f32 "
        "{%0,%1,%2,%3}, {%4,%5,%6,%7}, {%8,%9}, {%0,%1,%2,%3};"
        : "+f"(c[0]), "+f"(c[1]), "+f"(c[2]), "+f"(c[3])
        : "r"(a[0]), "r"(a[1]), "r"(a[2]), "r"(a[3]), "r"(b[0]), "r"(b[1]));
}

// ---------------- K0: zero accumulators ----------------
__global__ void k0_init() {
    if (threadIdx.x < 4) g_acc[threadIdx.x] = 0.f;
}

// ---------------- K1: inverse degrees (column sums of g), MLP=16 ----------------
__global__ void k1_deg(const float* __restrict__ g) {
    int idx = blockIdx.x * blockDim.x + threadIdx.x;   // b*N + n
    if (idx >= Bb * Nn) return;
    int b = idx >> 9;
    int n = idx & (Nn - 1);
    const float* p = g + (size_t)b * Nn * Nn + n;
    float s0 = 0.f, s1 = 0.f, s2 = 0.f, s3 = 0.f;
    for (int i = 0; i < Nn; i += 16) {
        float v[16];
        #pragma unroll
        for (int j = 0; j < 16; j++) v[j] = p[(size_t)(i + j) * Nn];
        #pragma unroll
        for (int j = 0; j < 16; j += 4) {
            s0 += v[j]; s1 += v[j + 1]; s2 += v[j + 2]; s3 += v[j + 3];
        }
    }
    g_inv_deg[idx] = 1.f / ((s0 + s1) + (s2 + s3));
}

// ---------------- K2: YsT[b][l][k] = ((h @ W_s)[k][l]) * inv_deg[b][k] ----------
#define BM 128
#define BN 64
#define BK 16
__global__ void __launch_bounds__(256) k2_hws(const float* __restrict__ h,
                                              const float* __restrict__ W_s) {
    __shared__ __align__(16) float As[BK][BM + 4];
    __shared__ __align__(16) float Bs[BK][BN];
    int m0 = blockIdx.x * BM;
    int tid = threadIdx.x;
    int tx = tid & 15;
    int ty = tid >> 4;
    float acc[8][4];
    #pragma unroll
    for (int i = 0; i < 8; i++)
        #pragma unroll
        for (int j = 0; j < 4; j++) acc[i][j] = 0.f;

    for (int k0 = 0; k0 < Ff; k0 += BK) {
        #pragma unroll
        for (int jj = 0; jj < 2; jj++) {
            int f4 = tid + 256 * jj;
            int row = f4 >> 2;
            int c4 = f4 & 3;
            float4 v = *(const float4*)&h[(size_t)(m0 + row) * Ff + k0 + c4 * 4];
            As[c4 * 4 + 0][row] = v.x;
            As[c4 * 4 + 1][row] = v.y;
            As[c4 * 4 + 2][row] = v.z;
            As[c4 * 4 + 3][row] = v.w;
        }
        {
            int row = tid >> 4;
            int c4 = tid & 15;
            float4 v = *(const float4*)&W_s[(size_t)(k0 + row) * Ll + c4 * 4];
            *(float4*)&Bs[row][c4 * 4] = v;
        }
        __syncthreads();
        #pragma unroll
        for (int k = 0; k < BK; k++) {
            float4 a0 = *(const float4*)&As[k][ty * 8];
            float4 a1 = *(const float4*)&As[k][ty * 8 + 4];
            float4 bv = *(const float4*)&Bs[k][tx * 4];
            float a[8] = {a0.x, a0.y, a0.z, a0.w, a1.x, a1.y, a1.z, a1.w};
            float bb[4] = {bv.x, bv.y, bv.z, bv.w};
            #pragma unroll
            for (int i = 0; i < 8; i++)
                #pragma unroll
                for (int j = 0; j < 4; j++) acc[i][j] += a[i] * bb[j];
        }
        __syncthreads();
    }
    int b = m0 >> 9;
    int node0 = (m0 & 511) + ty * 8;
    float idv[8];
    *(float4*)&idv[0] = *(const float4*)&g_inv_deg[m0 + ty * 8];
    *(float4*)&idv[4] = *(const float4*)&g_inv_deg[m0 + ty * 8 + 4];
    #pragma unroll
    for (int j = 0; j < 4; j++) {
        int l = tx * 4 + j;
        float* dst = g_YsT + ((size_t)b * Ll + l) * Nn + node0;
        float4 u, w;
        u.x = acc[0][j] * idv[0]; u.y = acc[1][j] * idv[1];
        u.z = acc[2][j] * idv[2]; u.w = acc[3][j] * idv[3];
        w.x = acc[4][j] * idv[4]; w.y = acc[5][j] * idv[5];
        w.z = acc[6][j] * idv[6]; w.w = acc[7][j] * idv[7];
        *(float4*)dst = u;
        *(float4*)(dst + 4) = w;
    }
}

// ================= K3: h1 = elu(g @ Ys + b_s) via mma.sync tf32 ==================
#define K3_AST 16384        // A stage bytes (128 rows x 128B)
#define K3_BST 8192         // B stage bytes (64 rows x 128B)
#define K3_DYN (2 * K3_AST + 2 * K3_BST)   // 49152 = 48KB exactly (no opt-in)

__device__ __forceinline__ uint32_t tile_addr(int row, int k) {
    int c = k >> 2;
    int slot = c ^ (row & 7);
    return (uint32_t)(((row << 3) + slot) * 16 + (k & 3) * 4);
}

__device__ __forceinline__ void k3_stage(int s, int tid, const float* __restrict__ Ag,
                                         const float* __restrict__ Bg,
                                         uint32_t smA, uint32_t smB) {
    int buf = s & 1;
    int k0 = s * 32;
    uint32_t ad = smA + buf * K3_AST;
    #pragma unroll
    for (int it = 0; it < 8; it++) {
        int idx = it * 128 + tid;
        int m = idx >> 3, c = idx & 7;
        cp_async16(ad + (uint32_t)((((m << 3) + (c ^ (m & 7))) << 4)),
                   Ag + (size_t)m * Nn + k0 + c * 4);
    }
    uint32_t bd = smB + buf * K3_BST;
    #pragma unroll
    for (int it = 0; it < 4; it++) {
        int idx = it * 128 + tid;
        int n = idx >> 3, c = idx & 7;
        cp_async16(bd + (uint32_t)((((n << 3) + (c ^ (n & 7))) << 4)),
                   Bg + (size_t)n * Nn + k0 + c * 4);
    }
    CP_COMMIT();
}

__global__ void __launch_bounds__(128, 4) k3_mma(const float* __restrict__ g,
                                                 const float* __restrict__ b_s) {
    extern __shared__ __align__(16) char dsm[];
    uint32_t smA = smem_u32(dsm);
    uint32_t smB = smA + 2 * K3_AST;

    int b = blockIdx.y;
    int m0 = blockIdx.x * 128;
    const float* Ag = g + ((size_t)b * Nn + m0) * Nn;
    const float* Bg = g_YsT + (size_t)b * Ll * Nn;

    int tid = threadIdx.x;
    int lane = tid & 31, wid = tid >> 5;
    int wm = wid & 1, wn = wid >> 1;       // warp grid 2(M) x 2(N)

    float acc[4][4][4];
    #pragma unroll
    for (int mt = 0; mt < 4; mt++)
        #pragma unroll
        for (int nt = 0; nt < 4; nt++)
            #pragma unroll
            for (int r = 0; r < 4; r++) acc[mt][nt][r] = 0.f;

    k3_stage(0, tid, Ag, Bg, smA, smB);
    k3_stage(1, tid, Ag, Bg, smA, smB);

    for (int s = 0; s < 16; s++) {
        if (s < 15) { CP_WAIT_1(); } else { CP_WAIT_0(); }
        __syncthreads();
        int buf = s & 1;
        uint32_t aB = smA + buf * K3_AST;
        uint32_t bB = smB + buf * K3_BST;
        #pragma unroll
        for (int j = 0; j < 4; j++) {
            int kl0 = j * 8 + (lane & 3);
            uint32_t af[4][4], bf[4][2];
            #pragma unroll
            for (int mt = 0; mt < 4; mt++) {
                int m = wm * 64 + mt * 16 + (lane >> 2);
                af[mt][0] = lds_tf32(aB + tile_addr(m, kl0));
                af[mt][1] = lds_tf32(aB + tile_addr(m + 8, kl0));
                af[mt][2] = lds_tf32(aB + tile_addr(m, kl0 + 4));
                af[mt][3] = lds_tf32(aB + tile_addr(m + 8, kl0 + 4));
            }
            #pragma unroll
            for (int nt = 0; nt < 4; nt++) {
                int n = wn * 32 + nt * 8 + (lane >> 2);
                bf[nt][0] = lds_tf32(bB + tile_addr(n, kl0));
                bf[nt][1] = lds_tf32(bB + tile_addr(n, kl0 + 4));
            }
            #pragma unroll
            for (int mt = 0; mt < 4; mt++)
                #pragma unroll
                for (int nt = 0; nt < 4; nt++)
                    mma_tf32(acc[mt][nt], af[mt], bf[nt]);
        }
        __syncthreads();
        if (s + 2 < 16) k3_stage(s + 2, tid, Ag, Bg, smA, smB);
    }

    // epilogue: bias (LDG, L1-hot) + ELU, float2 stores
    #pragma unroll
    for (int mt = 0; mt < 4; mt++) {
        #pragma unroll
        for (int nt = 0; nt < 4; nt++) {
            int row = wm * 64 + mt * 16 + (lane >> 2);
            int col = wn * 32 + nt * 8 + (lane & 3) * 2;
            float bs0 = __ldg(&b_s[col]), bs1 = __ldg(&b_s[col + 1]);
            float* o = g_h1 + ((size_t)b * Nn + m0 + row) * Ll + col;
            float2 v0 = make_float2(elu1(acc[mt][nt][0] + bs0), elu1(acc[mt][nt][1] + bs1));
            *(float2*)o = v0;
            float2 v1 = make_float2(elu1(acc[mt][nt][2] + bs0), elu1(acc[mt][nt][3] + bs1));
            *(float2*)(o + 8 * Ll) = v1;
        }
    }
}

// ---------------- K4: q = (h1 @ [W_mu|W_lv]) * inv_deg  (warp per row) ------------
__global__ void k4_q(const float* __restrict__ Wmu, const float* __restrict__ Wlv) {
    int warp = (blockIdx.x * blockDim.x + threadIdx.x) >> 5;
    int lane = threadIdx.x & 31;
    if (warp >= Bb * Nn) return;
    const float* r = g_h1 + (size_t)warp * Ll;
    float a0 = r[lane], a1 = r[lane + 32];
    float pm = a0 * Wmu[lane] + a1 * Wmu[lane + 32];
    float pl = a0 * Wlv[lane] + a1 * Wlv[lane + 32];
    #pragma unroll
    for (int o = 16; o; o >>= 1) {
        pm += __shfl_down_sync(0xffffffffu, pm, o);
        pl += __shfl_down_sync(0xffffffffu, pl, o);
    }
    if (lane == 0) {
        float id = g_inv_deg[warp];
        g_q[warp] = make_float2(pm * id, pl * id);
    }
}

// ---- K5: mu/lv matvec + reparam + sigmoid + KL (warp per row, full row in flight)
__global__ void __launch_bounds__(256) k5_muvlv(const float* __restrict__ g,
                                                const float* __restrict__ eps,
                                                const float* __restrict__ bmu,
                                                const float* __restrict__ blv,
                                                const float* __restrict__ beta) {
    int gw = (blockIdx.x * blockDim.x + threadIdx.x) >> 5;   // b*N + i
    int lane = threadIdx.x & 31;
    int wib = threadIdx.x >> 5;
    __shared__ float sred[8];
    float t = 0.f;
    {
        int b = gw >> 9;
        const float4* row4 = (const float4*)(g + (size_t)gw * Nn);
        const float4* q4 = (const float4*)(g_q + (size_t)b * Nn);
        float4 gv[4];
        #pragma unroll
        for (int tt = 0; tt < 4; tt++) gv[tt] = row4[lane + 32 * tt];   // 2KB row in flight
        float am = 0.f, al = 0.f;
        #pragma unroll
        for (int tt = 0; tt < 4; tt++) {
            int idx = lane + 32 * tt;
            float4 qa = q4[2 * idx];
            float4 qb = q4[2 * idx + 1];
            am += gv[tt].x * qa.x + gv[tt].y * qa.z + gv[tt].z * qb.x + gv[tt].w * qb.z;
            al += gv[tt].x * qa.y + gv[tt].y * qa.w + gv[tt].z * qb.y + gv[tt].w * qb.w;
        }
        #pragma unroll
        for (int o = 16; o; o >>= 1) {
            am += __shfl_down_sync(0xffffffffu, am, o);
            al += __shfl_down_sync(0xffffffffu, al, o);
        }
        if (lane == 0) {
            float mu = elu1(am + bmu[0]);
            float lv = elu1(al + blv[0]);
            float z = mu + eps[gw] * expf(0.5f * lv);
            float v = 1.f / (1.f + expf(-beta[0] * z));
            g_v[gw] = v;
            g_vd[gw] = v * g_inv_deg[gw];
            t = 1.f + 2.f * lv - mu * mu - expf(2.f * lv);
        }
    }
    if (lane == 0) sred[wib] = t;
    __syncthreads();
    if (threadIdx.x == 0) {
        float s = 0.f;
        #pragma unroll
        for (int i = 0; i < 8; i++) s += sred[i];
        atomicAdd(&g_acc[0], s);
    }
}

// ---- K6: decoder matvec + fused MSE (warp per row, full row in flight) ----------
__global__ void __launch_bounds__(256) k6_dec(const float* __restrict__ g,
                                              const float* __restrict__ Wdec,
                                              const float* __restrict__ bdec) {
    int gw = (blockIdx.x * blockDim.x + threadIdx.x) >> 5;   // b*N + i
    int lane = threadIdx.x & 31;
    int wib = threadIdx.x >> 5;
    __shared__ float sred[8];
    float s = 0.f;
    {
        int b = gw >> 9;
        const float4* row4 = (const float4*)(g + (size_t)gw * Nn);
        const float4* vd4 = (const float4*)(g_vd + (size_t)b * Nn);
        float4 gv[4];
        #pragma unroll
        for (int tt = 0; tt < 4; tt++) gv[tt] = row4[lane + 32 * tt];
        float aw = 0.f;
        #pragma unroll
        for (int tt = 0; tt < 4; tt++) {
            int idx = lane + 32 * tt;
            float4 vv = vd4[idx];
            aw += gv[tt].x * vv.x + gv[tt].y * vv.y + gv[tt].z * vv.z + gv[tt].w * vv.w;
        }
        #pragma unroll
        for (int o = 16; o; o >>= 1) aw += __shfl_xor_sync(0xffffffffu, aw, o);
        const float2* h1r = (const float2*)(g_h1 + (size_t)gw * Ll);
        float2 hh = h1r[lane];
        float dv0 = elu1(aw * Wdec[2 * lane] + bdec[2 * lane]);
        float dv1 = elu1(aw * Wdec[2 * lane + 1] + bdec[2 * lane + 1]);
        float d0 = hh.x - dv0, d1 = hh.y - dv1;
        s = d0 * d0 + d1 * d1;
        #pragma unroll
        for (int o = 16; o; o >>= 1) s += __shfl_down_sync(0xffffffffu, s, o);
    }
    if (lane == 0) sred[wib] = s;
    __syncthreads();
    if (threadIdx.x == 0) {
        float t = 0.f;
        #pragma unroll
        for (int i = 0; i < 8; i++) t += sred[i];
        atomicAdd(&g_acc[1], t);
    }
}

// ---------------- K7: hp[b,l] = sum_n h1[b,n,l] * v[b,n] ----------------
__global__ void k7_pool() {
    int b = blockIdx.x;
    int l = threadIdx.x & 63;
    int seg = threadIdx.x >> 6;            // 0..3
    float s = 0.f;
    int n0 = seg * 128;
    for (int n = n0; n < n0 + 128; n++)
        s += g_h1[((size_t)b * Nn + n) * Ll + l] * g_v[b * Nn + n];
    __shared__ float sm[4][64];
    sm[seg][l] = s;
    __syncthreads();
    if (seg == 0)
        g_hp[b * Ll + l] = (sm[0][l] + sm[1][l]) + (sm[2][l] + sm[3][l]);
}

// ---------------- K8: classifier + log_softmax + nll/acc partials ----------------
__global__ void k8_cls(const float* __restrict__ W1, const float* __restrict__ b1,
                       const float* __restrict__ W2, const float* __restrict__ b2,
                       const int* __restrict__ labels) {
    int b = blockIdx.x;
    int t = threadIdx.x;                   // 128 threads
    __shared__ float hps[Ll];
    __shared__ float a1[Hh];
    __shared__ float lg[Cc];
    if (t < Ll) hps[t] = g_hp[b * Ll + t];
    __syncthreads();
    float acc = b1[t];
    #pragma unroll 8
    for (int l = 0; l < Ll; l++) acc += hps[l] * W1[l * Hh + t];
    a1[t] = elu1(acc);
    __syncthreads();
    if (t < Cc) {
        float s = b2[t];
        #pragma unroll 8
        for (int hh = 0; hh < Hh; hh++) s += a1[hh] * W2[hh * Cc + t];
        lg[t] = s;
    }
    __syncthreads();
    if (t == 0) {
        float mx = lg[0];
        int am = 0;
        #pragma unroll
        for (int c = 1; c < Cc; c++)
            if (lg[c] > mx) { mx = lg[c]; am = c; }
        float se = 0.f;
        #pragma unroll
        for (int c = 0; c < Cc; c++) se += expf(lg[c] - mx);
        float lse = mx + logf(se);
        int lab = labels[b];
        atomicAdd(&g_acc[2], -(lg[lab] - lse));
        atomicAdd(&g_acc[3], (am == lab) ? 1.f : 0.f);
    }
}

// ---------------- K9: finalize ----------------
__global__ void k9_final(float* out) {
    const float M = (float)(Bb * Nn);
    float kl = (-0.5f / M) * (g_acc[0] / M);
    float mse = g_acc[1] / (float)(Bb * Nn * Ll);
    float nll = g_acc[2] / (float)Bb;
    out[0] = nll + kl + mse;
    out[1] = g_acc[3] / (float)Bb;
}

// ---------------- launch ----------------
extern "C" void kernel_launch(void* const* d_in, const int* in_sizes, int n_in,
                              void* d_out, int out_size) {
    const float* g     = (const float*)d_in[0];
    const float* h     = (const float*)d_in[1];
    const int*   labels= (const int*)  d_in[2];
    const float* eps   = (const float*)d_in[3];
    const float* W_s   = (const float*)d_in[4];
    const float* b_s   = (const float*)d_in[5];
    const float* W_mu  = (const float*)d_in[6];
    const float* b_mu  = (const float*)d_in[7];
    const float* W_lv  = (const float*)d_in[8];
    const float* b_lv  = (const float*)d_in[9];
    const float* W_dec = (const float*)d_in[10];
    const float* b_dec = (const float*)d_in[11];
    const float* W1    = (const float*)d_in[12];
    const float* b1    = (const float*)d_in[13];
    const float* W2    = (const float*)d_in[14];
    const float* b2    = (const float*)d_in[15];
    const float* beta  = (const float*)d_in[16];
    float* out = (float*)d_out;

    k0_init<<<1, 32>>>();
    k1_deg<<<(Bb * Nn) / 256, 256>>>(g);
    k2_hws<<<(Bb * Nn) / BM, 256>>>(h, W_s);
    k3_mma<<<dim3(Nn / 128, Bb), 128, K3_DYN>>>(g, b_s);
    k4_q<<<(Bb * Nn * 32) / 256, 256>>>(W_mu, W_lv);
    k5_muvlv<<<(Bb * Nn * 32) / 256, 256>>>(g, eps, b_mu, b_lv, beta);
    k6_dec<<<(Bb * Nn * 32) / 256, 256>>>(g, W_dec, b_dec);
    k7_pool<<<Bb, 256>>>();
    k8_cls<<<Bb, Hh>>>(W1, b1, W2, b2, labels);
    k9_final<<<1, 1>>>(out);
}

// round 12
// speedup vs baseline: 1.0119x; 1.0119x over previous
#include <cuda_runtime.h>
#include <cuda_bf16.h>
#include <cstdint>
#include <math.h>

// Problem constants
#define Bb 128
#define Nn 512
#define Ff 128
#define Ll 64
#define Hh 128
#define Cc 10

// ---------------- scratch (device globals; no allocation allowed) ----------------
__device__ float g_inv_deg[Bb * Nn];            // 1/deg[b,k]
__device__ float g_YsT[Bb * Ll * Nn];           // transposed: [B][L=64][N=512], ((h@W_s)/deg)^T
__device__ float g_h1[Bb * Nn * Ll];            // elu(g @ Ys + b_s)  [B,N,L]
__device__ float2 g_q[Bb * Nn];                 // (h1@W_mu, h1@W_lv)/deg
__device__ float g_v[Bb * Nn];                  // sigmoid(beta*z)
__device__ float g_vd[Bb * Nn];                 // v / deg
__device__ float g_hp[Bb * Ll];                 // pooled features
__device__ float g_acc[4];                      // [kl_sum, mse_sum, nll_sum, acc_sum]

__device__ __forceinline__ float elu1(float x) { return x > 0.f ? x : expm1f(x); }

// ======================= PTX helpers (base ISA only) =============================
__device__ __forceinline__ uint32_t smem_u32(const void* p) {
    uint32_t a;
    asm("{ .reg .u64 t; cvta.to.shared.u64 t, %1; cvt.u32.u64 %0, t; }" : "=r"(a) : "l"(p));
    return a;
}
__device__ __forceinline__ void cp_async16(uint32_t dst, const void* src) {
    asm volatile("cp.async.cg.shared.global [%0], [%1], 16;" :: "r"(dst), "l"(src) : "memory");
}
#define CP_COMMIT()  asm volatile("cp.async.commit_group;" ::: "memory")
#define CP_WAIT_1()  asm volatile("cp.async.wait_group 1;" ::: "memory")
#define CP_WAIT_0()  asm volatile("cp.async.wait_group 0;" ::: "memory")

// load fp32 from smem and convert to tf32 (round-to-nearest)
__device__ __forceinline__ uint32_t lds_tf32(uint32_t addr) {
    float v;
    asm volatile("ld.shared.f32 %0, [%1];" : "=f"(v) : "r"(addr));
    uint32_t r;
    asm volatile("cvt.rna.tf32.f32 %0, %1;" : "=r"(r) : "f"(v));
    return r;
}
__device__ __forceinline__ void mma_tf32(float* c, const uint32_t* a, const uint32_t* b) {
    asm volatile(
        "mma.sync.aligned.m16n8k8.row.col.f32.tf32.tf32.f32 "
        "{%0,%1,%2,%3}, {%4,%5,%6,%7}, {%8,%9}, {%0,%1,%2,%3};"
        : "+f"(c[0]), "+f"(c[1]), "+f"(c[2]), "+f"(c[3])
        : "r"(a[0]), "r"(a[1]), "r"(a[2]), "r"(a[3]), "r"(b[0]), "r"(b[1]));
}

// ---------------- K0: zero accumulators ----------------
__global__ void k0_init() {
    if (threadIdx.x < 4) g_acc[threadIdx.x] = 0.f;
}

// ---------------- K1: inverse degrees (column sums of g), MLP=16 ----------------
__global__ void k1_deg(const float* __restrict__ g) {
    int idx = blockIdx.x * blockDim.x + threadIdx.x;   // b*N + n
    if (idx >= Bb * Nn) return;
    int b = idx >> 9;
    int n = idx & (Nn - 1);
    const float* p = g + (size_t)b * Nn * Nn + n;
    float s0 = 0.f, s1 = 0.f, s2 = 0.f, s3 = 0.f;
    for (int i = 0; i < Nn; i += 16) {
        float v[16];
        #pragma unroll
        for (int j = 0; j < 16; j++) v[j] = p[(size_t)(i + j) * Nn];
        #pragma unroll
        for (int j = 0; j < 16; j += 4) {
            s0 += v[j]; s1 += v[j + 1]; s2 += v[j + 2]; s3 += v[j + 3];
        }
    }
    g_inv_deg[idx] = 1.f / ((s0 + s1) + (s2 + s3));
}

// ---------------- K2: YsT[b][l][k] = ((h @ W_s)[k][l]) * inv_deg[b][k] ----------
#define BM 128
#define BN 64
#define BK 16
__global__ void __launch_bounds__(256) k2_hws(const float* __restrict__ h,
                                              const float* __restrict__ W_s) {
    __shared__ __align__(16) float As[BK][BM + 4];
    __shared__ __align__(16) float Bs[BK][BN];
    int m0 = blockIdx.x * BM;
    int tid = threadIdx.x;
    int tx = tid & 15;
    int ty = tid >> 4;
    float acc[8][4];
    #pragma unroll
    for (int i = 0; i < 8; i++)
        #pragma unroll
        for (int j = 0; j < 4; j++) acc[i][j] = 0.f;

    for (int k0 = 0; k0 < Ff; k0 += BK) {
        #pragma unroll
        for (int jj = 0; jj < 2; jj++) {
            int f4 = tid + 256 * jj;
            int row = f4 >> 2;
            int c4 = f4 & 3;
            float4 v = *(const float4*)&h[(size_t)(m0 + row) * Ff + k0 + c4 * 4];
            As[c4 * 4 + 0][row] = v.x;
            As[c4 * 4 + 1][row] = v.y;
            As[c4 * 4 + 2][row] = v.z;
            As[c4 * 4 + 3][row] = v.w;
        }
        {
            int row = tid >> 4;
            int c4 = tid & 15;
            float4 v = *(const float4*)&W_s[(size_t)(k0 + row) * Ll + c4 * 4];
            *(float4*)&Bs[row][c4 * 4] = v;
        }
        __syncthreads();
        #pragma unroll
        for (int k = 0; k < BK; k++) {
            float4 a0 = *(const float4*)&As[k][ty * 8];
            float4 a1 = *(const float4*)&As[k][ty * 8 + 4];
            float4 bv = *(const float4*)&Bs[k][tx * 4];
            float a[8] = {a0.x, a0.y, a0.z, a0.w, a1.x, a1.y, a1.z, a1.w};
            float bb[4] = {bv.x, bv.y, bv.z, bv.w};
            #pragma unroll
            for (int i = 0; i < 8; i++)
                #pragma unroll
                for (int j = 0; j < 4; j++) acc[i][j] += a[i] * bb[j];
        }
        __syncthreads();
    }
    int b = m0 >> 9;
    int node0 = (m0 & 511) + ty * 8;
    float idv[8];
    *(float4*)&idv[0] = *(const float4*)&g_inv_deg[m0 + ty * 8];
    *(float4*)&idv[4] = *(const float4*)&g_inv_deg[m0 + ty * 8 + 4];
    #pragma unroll
    for (int j = 0; j < 4; j++) {
        int l = tx * 4 + j;
        float* dst = g_YsT + ((size_t)b * Ll + l) * Nn + node0;
        float4 u, w;
        u.x = acc[0][j] * idv[0]; u.y = acc[1][j] * idv[1];
        u.z = acc[2][j] * idv[2]; u.w = acc[3][j] * idv[3];
        w.x = acc[4][j] * idv[4]; w.y = acc[5][j] * idv[5];
        w.z = acc[6][j] * idv[6]; w.w = acc[7][j] * idv[7];
        *(float4*)dst = u;
        *(float4*)(dst + 4) = w;
    }
}

// ================= K3: h1 = elu(g @ Ys + b_s) via mma.sync tf32 ==================
#define K3_AST 16384        // A stage bytes (128 rows x 128B)
#define K3_BST 8192         // B stage bytes (64 rows x 128B)
#define K3_DYN (2 * K3_AST + 2 * K3_BST)   // 49152 = 48KB exactly (no opt-in)

__device__ __forceinline__ uint32_t tile_addr(int row, int k) {
    int c = k >> 2;
    int slot = c ^ (row & 7);
    return (uint32_t)(((row << 3) + slot) * 16 + (k & 3) * 4);
}

__device__ __forceinline__ void k3_stage(int s, int tid, const float* __restrict__ Ag,
                                         const float* __restrict__ Bg,
                                         uint32_t smA, uint32_t smB) {
    int buf = s & 1;
    int k0 = s * 32;
    uint32_t ad = smA + buf * K3_AST;
    #pragma unroll
    for (int it = 0; it < 8; it++) {
        int idx = it * 128 + tid;
        int m = idx >> 3, c = idx & 7;
        cp_async16(ad + (uint32_t)((((m << 3) + (c ^ (m & 7))) << 4)),
                   Ag + (size_t)m * Nn + k0 + c * 4);
    }
    uint32_t bd = smB + buf * K3_BST;
    #pragma unroll
    for (int it = 0; it < 4; it++) {
        int idx = it * 128 + tid;
        int n = idx >> 3, c = idx & 7;
        cp_async16(bd + (uint32_t)((((n << 3) + (c ^ (n & 7))) << 4)),
                   Bg + (size_t)n * Nn + k0 + c * 4);
    }
    CP_COMMIT();
}

__global__ void __launch_bounds__(128, 4) k3_mma(const float* __restrict__ g,
                                                 const float* __restrict__ b_s) {
    extern __shared__ __align__(16) char dsm[];
    uint32_t smA = smem_u32(dsm);
    uint32_t smB = smA + 2 * K3_AST;

    int b = blockIdx.y;
    int m0 = blockIdx.x * 128;
    const float* Ag = g + ((size_t)b * Nn + m0) * Nn;
    const float* Bg = g_YsT + (size_t)b * Ll * Nn;

    int tid = threadIdx.x;
    int lane = tid & 31, wid = tid >> 5;
    int wm = wid & 1, wn = wid >> 1;       // warp grid 2(M) x 2(N)

    float acc[4][4][4];
    #pragma unroll
    for (int mt = 0; mt < 4; mt++)
        #pragma unroll
        for (int nt = 0; nt < 4; nt++)
            #pragma unroll
            for (int r = 0; r < 4; r++) acc[mt][nt][r] = 0.f;

    k3_stage(0, tid, Ag, Bg, smA, smB);
    k3_stage(1, tid, Ag, Bg, smA, smB);

    for (int s = 0; s < 16; s++) {
        if (s < 15) { CP_WAIT_1(); } else { CP_WAIT_0(); }
        __syncthreads();
        int buf = s & 1;
        uint32_t aB = smA + buf * K3_AST;
        uint32_t bB = smB + buf * K3_BST;
        #pragma unroll
        for (int j = 0; j < 4; j++) {
            int kl0 = j * 8 + (lane & 3);
            uint32_t af[4][4], bf[4][2];
            #pragma unroll
            for (int mt = 0; mt < 4; mt++) {
                int m = wm * 64 + mt * 16 + (lane >> 2);
                af[mt][0] = lds_tf32(aB + tile_addr(m, kl0));
                af[mt][1] = lds_tf32(aB + tile_addr(m + 8, kl0));
                af[mt][2] = lds_tf32(aB + tile_addr(m, kl0 + 4));
                af[mt][3] = lds_tf32(aB + tile_addr(m + 8, kl0 + 4));
            }
            #pragma unroll
            for (int nt = 0; nt < 4; nt++) {
                int n = wn * 32 + nt * 8 + (lane >> 2);
                bf[nt][0] = lds_tf32(bB + tile_addr(n, kl0));
                bf[nt][1] = lds_tf32(bB + tile_addr(n, kl0 + 4));
            }
            #pragma unroll
            for (int mt = 0; mt < 4; mt++)
                #pragma unroll
                for (int nt = 0; nt < 4; nt++)
                    mma_tf32(acc[mt][nt], af[mt], bf[nt]);
        }
        __syncthreads();
        if (s + 2 < 16) k3_stage(s + 2, tid, Ag, Bg, smA, smB);
    }

    // epilogue: bias (LDG, L1-hot) + ELU, float2 stores
    #pragma unroll
    for (int mt = 0; mt < 4; mt++) {
        #pragma unroll
        for (int nt = 0; nt < 4; nt++) {
            int row = wm * 64 + mt * 16 + (lane >> 2);
            int col = wn * 32 + nt * 8 + (lane & 3) * 2;
            float bs0 = __ldg(&b_s[col]), bs1 = __ldg(&b_s[col + 1]);
            float* o = g_h1 + ((size_t)b * Nn + m0 + row) * Ll + col;
            float2 v0 = make_float2(elu1(acc[mt][nt][0] + bs0), elu1(acc[mt][nt][1] + bs1));
            *(float2*)o = v0;
            float2 v1 = make_float2(elu1(acc[mt][nt][2] + bs0), elu1(acc[mt][nt][3] + bs1));
            *(float2*)(o + 8 * Ll) = v1;
        }
    }
}

// ---------------- K4: q = (h1 @ [W_mu|W_lv]) * inv_deg  (warp per row) ------------
__global__ void k4_q(const float* __restrict__ Wmu, const float* __restrict__ Wlv) {
    int warp = (blockIdx.x * blockDim.x + threadIdx.x) >> 5;
    int lane = threadIdx.x & 31;
    if (warp >= Bb * Nn) return;
    const float* r = g_h1 + (size_t)warp * Ll;
    float a0 = r[lane], a1 = r[lane + 32];
    float pm = a0 * Wmu[lane] + a1 * Wmu[lane + 32];
    float pl = a0 * Wlv[lane] + a1 * Wlv[lane + 32];
    #pragma unroll
    for (int o = 16; o; o >>= 1) {
        pm += __shfl_down_sync(0xffffffffu, pm, o);
        pl += __shfl_down_sync(0xffffffffu, pl, o);
    }
    if (lane == 0) {
        float id = g_inv_deg[warp];
        g_q[warp] = make_float2(pm * id, pl * id);
    }
}

// ---- K5: mu/lv matvec + reparam + sigmoid + KL (warp per row, full row in flight)
__global__ void __launch_bounds__(256) k5_muvlv(const float* __restrict__ g,
                                                const float* __restrict__ eps,
                                                const float* __restrict__ bmu,
                                                const float* __restrict__ blv,
                                                const float* __restrict__ beta) {
    int gw = (blockIdx.x * blockDim.x + threadIdx.x) >> 5;   // b*N + i
    int lane = threadIdx.x & 31;
    int wib = threadIdx.x >> 5;
    __shared__ float sred[8];
    float t = 0.f;
    {
        int b = gw >> 9;
        const float4* row4 = (const float4*)(g + (size_t)gw * Nn);
        const float4* q4 = (const float4*)(g_q + (size_t)b * Nn);
        float4 gv[4];
        #pragma unroll
        for (int tt = 0; tt < 4; tt++) gv[tt] = row4[lane + 32 * tt];   // 2KB row in flight
        float am = 0.f, al = 0.f;
        #pragma unroll
        for (int tt = 0; tt < 4; tt++) {
            int idx = lane + 32 * tt;
            float4 qa = q4[2 * idx];
            float4 qb = q4[2 * idx + 1];
            am += gv[tt].x * qa.x + gv[tt].y * qa.z + gv[tt].z * qb.x + gv[tt].w * qb.z;
            al += gv[tt].x * qa.y + gv[tt].y * qa.w + gv[tt].z * qb.y + gv[tt].w * qb.w;
        }
        #pragma unroll
        for (int o = 16; o; o >>= 1) {
            am += __shfl_down_sync(0xffffffffu, am, o);
            al += __shfl_down_sync(0xffffffffu, al, o);
        }
        if (lane == 0) {
            float mu = elu1(am + bmu[0]);
            float lv = elu1(al + blv[0]);
            float z = mu + eps[gw] * expf(0.5f * lv);
            float v = 1.f / (1.f + expf(-beta[0] * z));
            g_v[gw] = v;
            g_vd[gw] = v * g_inv_deg[gw];
            t = 1.f + 2.f * lv - mu * mu - expf(2.f * lv);
        }
    }
    if (lane == 0) sred[wib] = t;
    __syncthreads();
    if (threadIdx.x == 0) {
        float s = 0.f;
        #pragma unroll
        for (int i = 0; i < 8; i++) s += sred[i];
        atomicAdd(&g_acc[0], s);
    }
}

// ---- K6: decoder matvec + fused MSE (warp per row, full row in flight) ----------
__global__ void __launch_bounds__(256) k6_dec(const float* __restrict__ g,
                                              const float* __restrict__ Wdec,
                                              const float* __restrict__ bdec) {
    int gw = (blockIdx.x * blockDim.x + threadIdx.x) >> 5;   // b*N + i
    int lane = threadIdx.x & 31;
    int wib = threadIdx.x >> 5;
    __shared__ float sred[8];
    float s = 0.f;
    {
        int b = gw >> 9;
        const float4* row4 = (const float4*)(g + (size_t)gw * Nn);
        const float4* vd4 = (const float4*)(g_vd + (size_t)b * Nn);
        float4 gv[4];
        #pragma unroll
        for (int tt = 0; tt < 4; tt++) gv[tt] = row4[lane + 32 * tt];
        float aw = 0.f;
        #pragma unroll
        for (int tt = 0; tt < 4; tt++) {
            int idx = lane + 32 * tt;
            float4 vv = vd4[idx];
            aw += gv[tt].x * vv.x + gv[tt].y * vv.y + gv[tt].z * vv.z + gv[tt].w * vv.w;
        }
        #pragma unroll
        for (int o = 16; o; o >>= 1) aw += __shfl_xor_sync(0xffffffffu, aw, o);
        const float2* h1r = (const float2*)(g_h1 + (size_t)gw * Ll);
        float2 hh = h1r[lane];
        float dv0 = elu1(aw * Wdec[2 * lane] + bdec[2 * lane]);
        float dv1 = elu1(aw * Wdec[2 * lane + 1] + bdec[2 * lane + 1]);
        float d0 = hh.x - dv0, d1 = hh.y - dv1;
        s = d0 * d0 + d1 * d1;
        #pragma unroll
        for (int o = 16; o; o >>= 1) s += __shfl_down_sync(0xffffffffu, s, o);
    }
    if (lane == 0) sred[wib] = s;
    __syncthreads();
    if (threadIdx.x == 0) {
        float t = 0.f;
        #pragma unroll
        for (int i = 0; i < 8; i++) t += sred[i];
        atomicAdd(&g_acc[1], t);
    }
}

// ---------------- K7: hp[b,l] = sum_n h1[b,n,l] * v[b,n] ----------------
__global__ void k7_pool() {
    int b = blockIdx.x;
    int l = threadIdx.x & 63;
    int seg = threadIdx.x >> 6;            // 0..3
    float s = 0.f;
    int n0 = seg * 128;
    for (int n = n0; n < n0 + 128; n++)
        s += g_h1[((size_t)b * Nn + n) * Ll + l] * g_v[b * Nn + n];
    __shared__ float sm[4][64];
    sm[seg][l] = s;
    __syncthreads();
    if (seg == 0)
        g_hp[b * Ll + l] = (sm[0][l] + sm[1][l]) + (sm[2][l] + sm[3][l]);
}

// ---------------- K8: classifier + log_softmax + nll/acc partials ----------------
__global__ void k8_cls(const float* __restrict__ W1, const float* __restrict__ b1,
                       const float* __restrict__ W2, const float* __restrict__ b2,
                       const int* __restrict__ labels) {
    int b = blockIdx.x;
    int t = threadIdx.x;                   // 128 threads
    __shared__ float hps[Ll];
    __shared__ float a1[Hh];
    __shared__ float lg[Cc];
    if (t < Ll) hps[t] = g_hp[b * Ll + t];
    __syncthreads();
    float acc = b1[t];
    #pragma unroll 8
    for (int l = 0; l < Ll; l++) acc += hps[l] * W1[l * Hh + t];
    a1[t] = elu1(acc);
    __syncthreads();
    if (t < Cc) {
        float s = b2[t];
        #pragma unroll 8
        for (int hh = 0; hh < Hh; hh++) s += a1[hh] * W2[hh * Cc + t];
        lg[t] = s;
    }
    __syncthreads();
    if (t == 0) {
        float mx = lg[0];
        int am = 0;
        #pragma unroll
        for (int c = 1; c < Cc; c++)
            if (lg[c] > mx) { mx = lg[c]; am = c; }
        float se = 0.f;
        #pragma unroll
        for (int c = 0; c < Cc; c++) se += expf(lg[c] - mx);
        float lse = mx + logf(se);
        int lab = labels[b];
        atomicAdd(&g_acc[2], -(lg[lab] - lse));
        atomicAdd(&g_acc[3], (am == lab) ? 1.f : 0.f);
    }
}

// ---------------- K9: finalize ----------------
__global__ void k9_final(float* out) {
    const float M = (float)(Bb * Nn);
    float kl = (-0.5f / M) * (g_acc[0] / M);
    float mse = g_acc[1] / (float)(Bb * Nn * Ll);
    float nll = g_acc[2] / (float)Bb;
    out[0] = nll + kl + mse;
    out[1] = g_acc[3] / (float)Bb;
}

// ---------------- launch ----------------
extern "C" void kernel_launch(void* const* d_in, const int* in_sizes, int n_in,
                              void* d_out, int out_size) {
    const float* g     = (const float*)d_in[0];
    const float* h     = (const float*)d_in[1];
    const int*   labels= (const int*)  d_in[2];
    const float* eps   = (const float*)d_in[3];
    const float* W_s   = (const float*)d_in[4];
    const float* b_s   = (const float*)d_in[5];
    const float* W_mu  = (const float*)d_in[6];
    const float* b_mu  = (const float*)d_in[7];
    const float* W_lv  = (const float*)d_in[8];
    const float* b_lv  = (const float*)d_in[9];
    const float* W_dec = (const float*)d_in[10];
    const float* b_dec = (const float*)d_in[11];
    const float* W1    = (const float*)d_in[12];
    const float* b1    = (const float*)d_in[13];
    const float* W2    = (const float*)d_in[14];
    const float* b2    = (const float*)d_in[15];
    const float* beta  = (const float*)d_in[16];
    float* out = (float*)d_out;

    k0_init<<<1, 32>>>();
    k1_deg<<<(Bb * Nn) / 256, 256>>>(g);
    k2_hws<<<(Bb * Nn) / BM, 256>>>(h, W_s);
    k3_mma<<<dim3(Nn / 128, Bb), 128, K3_DYN>>>(g, b_s);
    k4_q<<<(Bb * Nn * 32) / 256, 256>>>(W_mu, W_lv);
    k5_muvlv<<<(Bb * Nn * 32) / 256, 256>>>(g, eps, b_mu, b_lv, beta);
    k6_dec<<<(Bb * Nn * 32) / 256, 256>>>(g, W_dec, b_dec);
    k7_pool<<<Bb, 256>>>();
    k8_cls<<<Bb, Hh>>>(W1, b1, W2, b2, labels);
    k9_final<<<1, 1>>>(out);
}